// round 4
// baseline (speedup 1.0000x reference)
#include <cuda_runtime.h>

#define BB 32
#define NN 64
#define DD 128
#define GH 256
#define KC 32   // K-chunk for staged weight tiles

// Packed fp32x2 FMA (Blackwell sm_103a): d = a*b + d, two lanes per instr.
#define FFMA2(d, a, b) \
    asm("fma.rn.f32x2 %0, %1, %2, %0;" : "+l"(d) : "l"(a), "l"(b))
#define PACK2(dst, f) \
    asm("mov.b64 %0, {%1, %1};" : "=l"(dst) : "r"(__float_as_uint(f)))
#define UNPACK2(lo, hi, v) \
    asm("mov.b64 {%0, %1}, %2;" : "=r"(lo), "=r"(hi) : "l"(v))

// Scratch (allocation-free rule: __device__ globals)
__device__ float g_base[BB * NN * GH];     // [b][j][k] : x[j] @ W0[0:128]
__device__ float g_rowc[BB * NN * GH];     // [b][i][k] : x[i] @ W0[128:256] + q @ W0[256:384] + b0
__device__ float g_partial[BB * NN * GH];  // per-(batch,i) partial sums of relations

// -------------------------------------------------------------------------
// Kernel 1: layer-0 factorization precompute.
// grid (8, B), 256 threads. Each block handles 8 "i" rows of one batch.
// -------------------------------------------------------------------------
__global__ void precomp_kernel(const float* __restrict__ x,
                               const float* __restrict__ q,
                               const float* __restrict__ w0,
                               const float* __restrict__ b0) {
    const int batch = blockIdx.y;
    const int i0 = blockIdx.x * 8;
    const int k = threadIdx.x;  // 0..255 output column

    __shared__ float xs[8][DD];
    __shared__ float qs[DD];

    for (int idx = threadIdx.x; idx < 8 * DD; idx += 256) {
        int r = idx >> 7, d = idx & (DD - 1);
        xs[r][d] = x[(batch * NN + i0 + r) * DD + d];
    }
    if (threadIdx.x < DD) qs[threadIdx.x] = q[batch * DD + threadIdx.x];
    __syncthreads();

    float accA[8], accB[8];
#pragma unroll
    for (int r = 0; r < 8; ++r) { accA[r] = 0.f; accB[r] = 0.f; }

#pragma unroll 4
    for (int d = 0; d < DD; ++d) {
        float wa = w0[d * GH + k];            // rows [0,128)   -> multiplies x[j] (xi part)
        float wb = w0[(DD + d) * GH + k];     // rows [128,256) -> multiplies x[i] (xj part)
#pragma unroll
        for (int r = 0; r < 8; ++r) {
            accA[r] += xs[r][d] * wa;
            accB[r] += xs[r][d] * wb;
        }
    }

    float qacc = 0.f;
#pragma unroll 4
    for (int d = 0; d < DD; ++d)
        qacc += qs[d] * w0[(2 * DD + d) * GH + k];  // rows [256,384) -> q part
    qacc += b0[k];

#pragma unroll
    for (int r = 0; r < 8; ++r) {
        g_base[(batch * NN + i0 + r) * GH + k] = accA[r];
        g_rowc[(batch * NN + i0 + r) * GH + k] = accB[r] + qacc;
    }
}

// -------------------------------------------------------------------------
// Kernel 2: fused g-MLP layers 1+2 + pair reduction, FFMA2 inner loops.
// grid (N, B) = (64, 32); block = 256 threads handles the 64 pairs (i fixed,
// j = 0..63) as a 64x256 tile. Per-thread 8x8 register tile, stored as
// 32 packed f32x2 accumulators (pairs along the column dim).
//   warp id a (0..7)  -> j-block  ja = a*8
//   lane id b (0..31) -> col-block nb = b*8
// -------------------------------------------------------------------------
extern __shared__ float smem_dyn[];

__global__ void __launch_bounds__(256, 2)
rn_main_kernel(const float* __restrict__ w1, const float* __restrict__ b1,
               const float* __restrict__ w2, const float* __restrict__ b2) {
    const int batch = blockIdx.y;
    const int i = blockIdx.x;

    float* h0s   = smem_dyn;                 // 64*256
    float* wb    = h0s + 64 * GH;            // KC*256
    float* rowcs = wb + KC * GH;             // 256
    float* red   = rowcs + GH;               // 8*256

    const int tid = threadIdx.x;
    const int a = tid >> 5;       // warp id -> j block
    const int b = tid & 31;       // lane id -> col block
    const int ja = a * 8;
    const int nb = b * 8;

    // rowc for this i
    rowcs[tid] = g_rowc[(batch * NN + i) * GH + tid];
    __syncthreads();

    // h0 = relu(base[j] + rowc[i])  (coalesced global read, conflict-free STS)
    const float* basep = &g_base[batch * NN * GH];
    for (int idx = tid; idx < 64 * GH; idx += 256) {
        float v = basep[idx] + rowcs[idx & (GH - 1)];
        h0s[idx] = v > 0.f ? v : 0.f;
    }

    // acc2[jj*4+p] holds output cols (nb+2p, nb+2p+1) for pair-row ja+jj
    unsigned long long acc2[32];
#pragma unroll
    for (int t = 0; t < 32; ++t) acc2[t] = 0ull;

    // ---------------- layer 1: h1 = relu(h0 @ W1 + b1) ----------------
#pragma unroll 1
    for (int kc = 0; kc < GH; kc += KC) {
        __syncthreads();
        for (int idx = tid; idx < KC * GH; idx += 256)
            wb[idx] = w1[(kc + (idx >> 8)) * GH + (idx & (GH - 1))];
        __syncthreads();

        const float* h0base = h0s + ja * GH + kc;
#pragma unroll 4
        for (int kk = 0; kk < KC; ++kk) {
            ulonglong2 wA = *reinterpret_cast<const ulonglong2*>(&wb[kk * GH + nb]);
            ulonglong2 wB = *reinterpret_cast<const ulonglong2*>(&wb[kk * GH + nb + 4]);
#pragma unroll
            for (int jj = 0; jj < 8; ++jj) {
                unsigned long long hh;
                PACK2(hh, h0base[jj * GH + kk]);   // warp-broadcast LDS + pack
                FFMA2(acc2[jj * 4 + 0], hh, wA.x);
                FFMA2(acc2[jj * 4 + 1], hh, wA.y);
                FFMA2(acc2[jj * 4 + 2], hh, wB.x);
                FFMA2(acc2[jj * 4 + 3], hh, wB.y);
            }
        }
    }

    // bias + relu, write h1 into h0 buffer (conflict-free float4 STS)
    __syncthreads();   // all h0 reads complete before overwrite
    {
        float4 bv0 = *reinterpret_cast<const float4*>(&b1[nb]);
        float4 bv1 = *reinterpret_cast<const float4*>(&b1[nb + 4]);
#pragma unroll
        for (int jj = 0; jj < 8; ++jj) {
            unsigned int l0, h0u, l1, h1u, l2, h2u, l3, h3u;
            UNPACK2(l0, h0u, acc2[jj * 4 + 0]);
            UNPACK2(l1, h1u, acc2[jj * 4 + 1]);
            UNPACK2(l2, h2u, acc2[jj * 4 + 2]);
            UNPACK2(l3, h3u, acc2[jj * 4 + 3]);
            float4 v0, v1;
            v0.x = fmaxf(__uint_as_float(l0) + bv0.x, 0.f);
            v0.y = fmaxf(__uint_as_float(h0u) + bv0.y, 0.f);
            v0.z = fmaxf(__uint_as_float(l1) + bv0.z, 0.f);
            v0.w = fmaxf(__uint_as_float(h1u) + bv0.w, 0.f);
            v1.x = fmaxf(__uint_as_float(l2) + bv1.x, 0.f);
            v1.y = fmaxf(__uint_as_float(h2u) + bv1.y, 0.f);
            v1.z = fmaxf(__uint_as_float(l3) + bv1.z, 0.f);
            v1.w = fmaxf(__uint_as_float(h3u) + bv1.w, 0.f);
            *reinterpret_cast<float4*>(&h0s[(ja + jj) * GH + nb]) = v0;
            *reinterpret_cast<float4*>(&h0s[(ja + jj) * GH + nb + 4]) = v1;
        }
    }

#pragma unroll
    for (int t = 0; t < 32; ++t) acc2[t] = 0ull;

    // ---------------- layer 2: r = relu(h1 @ W2 + b2) ----------------
#pragma unroll 1
    for (int kc = 0; kc < GH; kc += KC) {
        __syncthreads();
        for (int idx = tid; idx < KC * GH; idx += 256)
            wb[idx] = w2[(kc + (idx >> 8)) * GH + (idx & (GH - 1))];
        __syncthreads();

        const float* h1base = h0s + ja * GH + kc;
#pragma unroll 4
        for (int kk = 0; kk < KC; ++kk) {
            ulonglong2 wA = *reinterpret_cast<const ulonglong2*>(&wb[kk * GH + nb]);
            ulonglong2 wB = *reinterpret_cast<const ulonglong2*>(&wb[kk * GH + nb + 4]);
#pragma unroll
            for (int jj = 0; jj < 8; ++jj) {
                unsigned long long hh;
                PACK2(hh, h1base[jj * GH + kk]);
                FFMA2(acc2[jj * 4 + 0], hh, wA.x);
                FFMA2(acc2[jj * 4 + 1], hh, wA.y);
                FFMA2(acc2[jj * 4 + 2], hh, wB.x);
                FFMA2(acc2[jj * 4 + 3], hh, wB.y);
            }
        }
    }

    // bias2 + relu + sum over this thread's 8 j's
    float rsum[8];
    {
        float4 bv0 = *reinterpret_cast<const float4*>(&b2[nb]);
        float4 bv1 = *reinterpret_cast<const float4*>(&b2[nb + 4]);
        float bias[8] = {bv0.x, bv0.y, bv0.z, bv0.w, bv1.x, bv1.y, bv1.z, bv1.w};
#pragma unroll
        for (int nn = 0; nn < 8; ++nn) rsum[nn] = 0.f;
#pragma unroll
        for (int jj = 0; jj < 8; ++jj) {
#pragma unroll
            for (int p = 0; p < 4; ++p) {
                unsigned int lo, hi;
                UNPACK2(lo, hi, acc2[jj * 4 + p]);
                float v0 = __uint_as_float(lo) + bias[2 * p];
                float v1 = __uint_as_float(hi) + bias[2 * p + 1];
                rsum[2 * p]     += (v0 > 0.f ? v0 : 0.f);
                rsum[2 * p + 1] += (v1 > 0.f ? v1 : 0.f);
            }
        }
    }

    // cross-warp reduce (deterministic, fixed order)
    __syncthreads();
#pragma unroll
    for (int nn = 0; nn < 8; ++nn) red[a * GH + nb + nn] = rsum[nn];
    __syncthreads();

    float s = 0.f;
#pragma unroll
    for (int w = 0; w < 8; ++w) s += red[w * GH + tid];
    g_partial[(batch * NN + i) * GH + tid] = s;
}

// -------------------------------------------------------------------------
// Kernel 3: reduce partials over i-blocks + f MLP. grid = B, 256 threads.
// -------------------------------------------------------------------------
__global__ void f_mlp_kernel(const float* __restrict__ fw0, const float* __restrict__ fb0,
                             const float* __restrict__ fw1, const float* __restrict__ fb1,
                             float* __restrict__ out) {
    const int batch = blockIdx.x;
    const int t = threadIdx.x;
    __shared__ float emb[GH];
    __shared__ float h[GH];

    float s = 0.f;
#pragma unroll 4
    for (int blk = 0; blk < NN; ++blk)
        s += g_partial[(batch * NN + blk) * GH + t];
    emb[t] = s;
    __syncthreads();

    float acc = fb0[t];
#pragma unroll 4
    for (int m = 0; m < GH; ++m) acc += emb[m] * fw0[m * GH + t];
    h[t] = acc > 0.f ? acc : 0.f;
    __syncthreads();

    if (t < 32) {
        float o = fb1[t];
#pragma unroll 4
        for (int n = 0; n < GH; ++n) o += h[n] * fw1[n * 32 + t];
        out[batch * 32 + t] = o;
    }
}

// -------------------------------------------------------------------------
extern "C" void kernel_launch(void* const* d_in, const int* in_sizes, int n_in,
                              void* d_out, int out_size) {
    const float* x    = (const float*)d_in[0];
    const float* q    = (const float*)d_in[1];
    const float* g_w0 = (const float*)d_in[2];
    const float* g_b0 = (const float*)d_in[3];
    const float* g_w1 = (const float*)d_in[4];
    const float* g_b1 = (const float*)d_in[5];
    const float* g_w2 = (const float*)d_in[6];
    const float* g_b2 = (const float*)d_in[7];
    const float* f_w0 = (const float*)d_in[8];
    const float* f_b0 = (const float*)d_in[9];
    const float* f_w1 = (const float*)d_in[10];
    const float* f_b1 = (const float*)d_in[11];
    float* out = (float*)d_out;

    precomp_kernel<<<dim3(8, BB), 256>>>(x, q, g_w0, g_b0);

    size_t smem_bytes = (size_t)(64 * GH + KC * GH + GH + 8 * GH) * sizeof(float); // 107520
    cudaFuncSetAttribute(rn_main_kernel, cudaFuncAttributeMaxDynamicSharedMemorySize,
                         (int)smem_bytes);
    rn_main_kernel<<<dim3(NN, BB), 256, smem_bytes>>>(g_w1, g_b1, g_w2, g_b2);

    f_mlp_kernel<<<BB, 256>>>(f_w0, f_b0, f_w1, f_b1, out);
}

// round 13
// speedup vs baseline: 1.4247x; 1.4247x over previous
#include <cuda_runtime.h>
#include <cuda_bf16.h>
#include <cstdint>

#define BB 32
#define NN 64
#define DD 128
#define GH 256

// ---------------- smem byte offsets (main kernel) ----------------
#define A_HI_OFF   0
#define A_LO_OFF   32768
#define B_OFF      65536         // two 64KB buffers
#define ROWC_OFF   196608
#define B1S_OFF    197632
#define B2S_OFF    198656
#define RED_OFF    199680
#define SMEM_TOTAL 201728

// ---------------- helpers ----------------
__device__ __forceinline__ uint32_t pack_bf2(__nv_bfloat16 lo, __nv_bfloat16 hi) {
    return ((uint32_t)__bfloat16_as_ushort(hi) << 16) | __bfloat16_as_ushort(lo);
}
__device__ __forceinline__ float relu_f(float v) { return v > 0.f ? v : 0.f; }
// A tile byte offset: row-major [64][256] bf16, 512B rows, 16B-chunk XOR swizzle
__device__ __forceinline__ int a_off(int row, int k) {
    return row * 512 + ((((k >> 3) ^ (row & 7))) << 4) + ((k & 7) << 1);
}
__device__ __forceinline__ uint32_t smem_addr_u32(const void* p) {
    return (uint32_t)__cvta_generic_to_shared(p);
}
__device__ __forceinline__ void cp_async16(uint32_t saddr, const void* gptr) {
    asm volatile("cp.async.ca.shared.global [%0], [%1], 16;" :: "r"(saddr), "l"(gptr));
}
#define CP_COMMIT() asm volatile("cp.async.commit_group;" ::: "memory")
#define CP_WAIT(N)  asm volatile("cp.async.wait_group %0;" :: "n"(N) : "memory")

#define MMA_BF16(D, A, B) \
    asm volatile("mma.sync.aligned.m16n8k16.row.col.f32.bf16.bf16.f32 " \
        "{%0,%1,%2,%3}, {%4,%5,%6,%7}, {%8,%9}, {%0,%1,%2,%3};" \
        : "+f"((D)[0]), "+f"((D)[1]), "+f"((D)[2]), "+f"((D)[3]) \
        : "r"((A)[0]), "r"((A)[1]), "r"((A)[2]), "r"((A)[3]), \
          "r"((B).x), "r"((B).y))

// ---------------- device scratch ----------------
__device__ float g_base[BB * NN * GH];
__device__ float g_rowc[BB * NN * GH];
__device__ float g_partial[BB * NN * GH];
// B fragments, per-lane register layout: uint2 [layer][part][kc][ks][ntg][lane]
__device__ __align__(16) uint2 g_wfrag[2 * 2 * 4 * 4 * 32 * 32];

// ---------------- kernel 0: build weight fragments ----------------
__global__ void setup_wfrag_kernel(const float* __restrict__ w1, const float* __restrict__ w2) {
    int idx = blockIdx.x * 256 + threadIdx.x;        // 0..65535
    int lane = idx & 31;
    int ntg  = (idx >> 5) & 31;
    int ks   = (idx >> 10) & 3;
    int kc   = (idx >> 12) & 3;
    int p    = (idx >> 14) & 1;
    int l    = (idx >> 15) & 1;
    const float* W = l ? w2 : w1;
    int n  = ntg * 8 + (lane >> 2);
    int k0 = kc * 64 + ks * 16 + (lane & 3) * 2;

    __nv_bfloat16 v[4];
#pragma unroll
    for (int t = 0; t < 4; ++t) {
        int k = k0 + (t >> 1) * 8 + (t & 1);
        float wv = W[k * GH + n];
        __nv_bfloat16 hi = __float2bfloat16(wv);
        v[t] = p ? __float2bfloat16(wv - __bfloat162float(hi)) : hi;
    }
    uint2 r;
    r.x = pack_bf2(v[0], v[1]);
    r.y = pack_bf2(v[2], v[3]);
    g_wfrag[idx] = r;
}

// ---------------- kernel 1: layer-0 factorization ----------------
__global__ void precomp_kernel(const float* __restrict__ x,
                               const float* __restrict__ q,
                               const float* __restrict__ w0,
                               const float* __restrict__ b0) {
    const int batch = blockIdx.y;
    const int i0 = blockIdx.x * 8;
    const int k = threadIdx.x;

    __shared__ float xs[8][DD];
    __shared__ float qs[DD];
    for (int idx = threadIdx.x; idx < 8 * DD; idx += 256) {
        int r = idx >> 7, d = idx & (DD - 1);
        xs[r][d] = x[(batch * NN + i0 + r) * DD + d];
    }
    if (threadIdx.x < DD) qs[threadIdx.x] = q[batch * DD + threadIdx.x];
    __syncthreads();

    float accA[8], accB[8];
#pragma unroll
    for (int r = 0; r < 8; ++r) { accA[r] = 0.f; accB[r] = 0.f; }
    float qacc = 0.f;

#pragma unroll 8
    for (int d = 0; d < DD; ++d) {
        float wa = w0[d * GH + k];
        float wb = w0[(DD + d) * GH + k];
        float wq = w0[(2 * DD + d) * GH + k];
        qacc += qs[d] * wq;
#pragma unroll
        for (int r = 0; r < 8; ++r) {
            accA[r] += xs[r][d] * wa;
            accB[r] += xs[r][d] * wb;
        }
    }
    qacc += b0[k];
#pragma unroll
    for (int r = 0; r < 8; ++r) {
        g_base[(batch * NN + i0 + r) * GH + k] = accA[r];
        g_rowc[(batch * NN + i0 + r) * GH + k] = accB[r] + qacc;
    }
}

// ---------------- kernel 2: split-bf16 tensor-core main ----------------
// grid (NN, BB). 8 warps: wm = w>>2 (rows 32), wn = w&3 (cols 64).
extern __shared__ char smem_raw[];

__global__ void __launch_bounds__(256, 1)
rn_mma_kernel(const float* __restrict__ b1, const float* __restrict__ b2) {
    const int batch = blockIdx.y;
    const int i = blockIdx.x;
    const int tid = threadIdx.x;
    const int w = tid >> 5;
    const int lane = tid & 31;
    const int wm = w >> 2;
    const int wn = w & 3;

    char* sm = smem_raw;
    float* rowcs = (float*)(sm + ROWC_OFF);
    float* b1s   = (float*)(sm + B1S_OFF);
    float* b2s   = (float*)(sm + B2S_OFF);
    float* red   = (float*)(sm + RED_OFF);

    rowcs[tid] = g_rowc[(batch * NN + i) * GH + tid];
    b1s[tid] = b1[tid];
    b2s[tid] = b2[tid];
    __syncthreads();

    // ---- build h0 split into A_hi / A_lo (bf16, swizzled) ----
    const float* bp = g_base + (size_t)(batch * NN) * GH;
#pragma unroll 4
    for (int t = 0; t < 32; ++t) {
        int pi = t * 256 + tid;          // 0..8191 pairs
        int row = pi >> 7;
        int k = (pi & 127) * 2;
        float2 v = *(const float2*)&bp[row * GH + k];
        float a0 = relu_f(v.x + rowcs[k]);
        float a1 = relu_f(v.y + rowcs[k + 1]);
        __nv_bfloat16 h0b = __float2bfloat16(a0);
        __nv_bfloat16 h1b = __float2bfloat16(a1);
        __nv_bfloat16 l0b = __float2bfloat16(a0 - __bfloat162float(h0b));
        __nv_bfloat16 l1b = __float2bfloat16(a1 - __bfloat162float(h1b));
        int off = a_off(row, k);
        *(uint32_t*)(sm + A_HI_OFF + off) = pack_bf2(h0b, h1b);
        *(uint32_t*)(sm + A_LO_OFF + off) = pack_bf2(l0b, l1b);
    }

    float acc[2][8][4];
#pragma unroll
    for (int mt = 0; mt < 2; ++mt)
#pragma unroll
        for (int nt = 0; nt < 8; ++nt)
#pragma unroll
            for (int e = 0; e < 4; ++e) acc[mt][nt][e] = 0.f;

    // prefetch chunk 0 (layer 0, kc 0)
    const uint4* wfrag4 = (const uint4*)g_wfrag;
    {
#pragma unroll
        for (int t = 0; t < 16; ++t) {
            int idx = t * 256 + tid;                 // 0..4095 uint4
            int part = idx >> 11, within = idx & 2047;
            cp_async16(smem_addr_u32(sm + B_OFF) + idx * 16,
                       wfrag4 + ((0 * 2 + part) * 4 + 0) * 2048 + within);
        }
        CP_COMMIT();
    }

#pragma unroll 1
    for (int c = 0; c < 8; ++c) {
        const int buf = c & 1;
        // prefetch chunk c+1 into other buffer
        if (c < 7) {
            int nl = (c + 1) >> 2, nkc = (c + 1) & 3, nbuf = (c + 1) & 1;
#pragma unroll
            for (int t = 0; t < 16; ++t) {
                int idx = t * 256 + tid;
                int part = idx >> 11, within = idx & 2047;
                cp_async16(smem_addr_u32(sm + B_OFF) + (size_t)nbuf * 65536 + idx * 16,
                           wfrag4 + ((nl * 2 + part) * 4 + nkc) * 2048 + within);
            }
            CP_COMMIT();
            CP_WAIT(1);
        } else {
            CP_WAIT(0);
        }
        __syncthreads();   // chunk c resident; all warps past previous iteration

        const uint2* Bs = (const uint2*)(sm + B_OFF + (size_t)buf * 65536);
        const int kc = c & 3;

#pragma unroll 1
        for (int ks = 0; ks < 4; ++ks) {
            const int kbase = kc * 64 + ks * 16;
            uint32_t ahi[2][4], alo[2][4];
#pragma unroll
            for (int mt = 0; mt < 2; ++mt) {
                int r0 = wm * 32 + mt * 16 + (lane >> 2);
                int r1 = r0 + 8;
                int kA = kbase + (lane & 3) * 2;
                int o00 = a_off(r0, kA), o10 = a_off(r1, kA);
                int o01 = a_off(r0, kA + 8), o11 = a_off(r1, kA + 8);
                ahi[mt][0] = *(const uint32_t*)(sm + A_HI_OFF + o00);
                ahi[mt][1] = *(const uint32_t*)(sm + A_HI_OFF + o10);
                ahi[mt][2] = *(const uint32_t*)(sm + A_HI_OFF + o01);
                ahi[mt][3] = *(const uint32_t*)(sm + A_HI_OFF + o11);
                alo[mt][0] = *(const uint32_t*)(sm + A_LO_OFF + o00);
                alo[mt][1] = *(const uint32_t*)(sm + A_LO_OFF + o10);
                alo[mt][2] = *(const uint32_t*)(sm + A_LO_OFF + o01);
                alo[mt][3] = *(const uint32_t*)(sm + A_LO_OFF + o11);
            }
#pragma unroll
            for (int nt2 = 0; nt2 < 4; ++nt2) {
                int ntgA = wn * 8 + nt2 * 2;
                uint2 bh0 = Bs[(0 * 4 + ks) * 1024 + ntgA * 32 + lane];
                uint2 bh1 = Bs[(0 * 4 + ks) * 1024 + (ntgA + 1) * 32 + lane];
                uint2 bl0 = Bs[(1 * 4 + ks) * 1024 + ntgA * 32 + lane];
                uint2 bl1 = Bs[(1 * 4 + ks) * 1024 + (ntgA + 1) * 32 + lane];
                // part hi*hi
                MMA_BF16(acc[0][nt2 * 2], ahi[0], bh0);
                MMA_BF16(acc[0][nt2 * 2 + 1], ahi[0], bh1);
                MMA_BF16(acc[1][nt2 * 2], ahi[1], bh0);
                MMA_BF16(acc[1][nt2 * 2 + 1], ahi[1], bh1);
                // part hi*lo
                MMA_BF16(acc[0][nt2 * 2], ahi[0], bl0);
                MMA_BF16(acc[0][nt2 * 2 + 1], ahi[0], bl1);
                MMA_BF16(acc[1][nt2 * 2], ahi[1], bl0);
                MMA_BF16(acc[1][nt2 * 2 + 1], ahi[1], bl1);
                // part lo*hi
                MMA_BF16(acc[0][nt2 * 2], alo[0], bh0);
                MMA_BF16(acc[0][nt2 * 2 + 1], alo[0], bh1);
                MMA_BF16(acc[1][nt2 * 2], alo[1], bh0);
                MMA_BF16(acc[1][nt2 * 2 + 1], alo[1], bh1);
            }
        }

        if (c == 3) {
            // ---- epilogue 1: h1 = relu(acc + b1) -> split bf16 -> A ----
            __syncthreads();   // all h0 reads complete
#pragma unroll
            for (int mt = 0; mt < 2; ++mt)
#pragma unroll
                for (int nt = 0; nt < 8; ++nt) {
                    int r0 = wm * 32 + mt * 16 + (lane >> 2);
                    int r1 = r0 + 8;
                    int col = wn * 64 + nt * 8 + (lane & 3) * 2;
                    float b0v = b1s[col], b1v = b1s[col + 1];
                    float v00 = relu_f(acc[mt][nt][0] + b0v);
                    float v01 = relu_f(acc[mt][nt][1] + b1v);
                    float v10 = relu_f(acc[mt][nt][2] + b0v);
                    float v11 = relu_f(acc[mt][nt][3] + b1v);
                    __nv_bfloat16 h00 = __float2bfloat16(v00), h01 = __float2bfloat16(v01);
                    __nv_bfloat16 h10 = __float2bfloat16(v10), h11 = __float2bfloat16(v11);
                    __nv_bfloat16 l00 = __float2bfloat16(v00 - __bfloat162float(h00));
                    __nv_bfloat16 l01 = __float2bfloat16(v01 - __bfloat162float(h01));
                    __nv_bfloat16 l10 = __float2bfloat16(v10 - __bfloat162float(h10));
                    __nv_bfloat16 l11 = __float2bfloat16(v11 - __bfloat162float(h11));
                    int o0 = a_off(r0, col), o1 = a_off(r1, col);
                    *(uint32_t*)(sm + A_HI_OFF + o0) = pack_bf2(h00, h01);
                    *(uint32_t*)(sm + A_HI_OFF + o1) = pack_bf2(h10, h11);
                    *(uint32_t*)(sm + A_LO_OFF + o0) = pack_bf2(l00, l01);
                    *(uint32_t*)(sm + A_LO_OFF + o1) = pack_bf2(l10, l11);
                }
#pragma unroll
            for (int mt = 0; mt < 2; ++mt)
#pragma unroll
                for (int nt = 0; nt < 8; ++nt)
#pragma unroll
                    for (int e = 0; e < 4; ++e) acc[mt][nt][e] = 0.f;
        }
        __syncthreads();   // safe to overwrite buf[(c+2)&1] next iteration
    }

    // ---- epilogue 2: relu(acc + b2), reduce over rows (j) ----
#pragma unroll
    for (int nt = 0; nt < 8; ++nt) {
        int col = wn * 64 + nt * 8 + (lane & 3) * 2;
        float b0v = b2s[col], b1v = b2s[col + 1];
        float s0 = relu_f(acc[0][nt][0] + b0v) + relu_f(acc[0][nt][2] + b0v)
                 + relu_f(acc[1][nt][0] + b0v) + relu_f(acc[1][nt][2] + b0v);
        float s1 = relu_f(acc[0][nt][1] + b1v) + relu_f(acc[0][nt][3] + b1v)
                 + relu_f(acc[1][nt][1] + b1v) + relu_f(acc[1][nt][3] + b1v);
        s0 += __shfl_xor_sync(0xffffffffu, s0, 4);
        s0 += __shfl_xor_sync(0xffffffffu, s0, 8);
        s0 += __shfl_xor_sync(0xffffffffu, s0, 16);
        s1 += __shfl_xor_sync(0xffffffffu, s1, 4);
        s1 += __shfl_xor_sync(0xffffffffu, s1, 8);
        s1 += __shfl_xor_sync(0xffffffffu, s1, 16);
        if (lane < 4) {
            red[wm * GH + col] = s0;
            red[wm * GH + col + 1] = s1;
        }
    }
    __syncthreads();
    g_partial[(batch * NN + i) * GH + tid] = red[tid] + red[GH + tid];
}

// ---------------- kernel 3: f MLP ----------------
__global__ void f_mlp_kernel(const float* __restrict__ fw0, const float* __restrict__ fb0,
                             const float* __restrict__ fw1, const float* __restrict__ fb1,
                             float* __restrict__ out) {
    const int batch = blockIdx.x;
    const int t = threadIdx.x;
    __shared__ float emb[GH];
    __shared__ float h[GH];

    float s = 0.f;
#pragma unroll 4
    for (int blk = 0; blk < NN; ++blk)
        s += g_partial[(batch * NN + blk) * GH + t];
    emb[t] = s;
    __syncthreads();

    float acc = fb0[t];
#pragma unroll 4
    for (int m = 0; m < GH; ++m) acc += emb[m] * fw0[m * GH + t];
    h[t] = acc > 0.f ? acc : 0.f;
    __syncthreads();

    if (t < 32) {
        float o = fb1[t];
#pragma unroll 4
        for (int n = 0; n < GH; ++n) o += h[n] * fw1[n * 32 + t];
        out[batch * 32 + t] = o;
    }
}

// ---------------- launch ----------------
extern "C" void kernel_launch(void* const* d_in, const int* in_sizes, int n_in,
                              void* d_out, int out_size) {
    const float* x    = (const float*)d_in[0];
    const float* q    = (const float*)d_in[1];
    const float* g_w0 = (const float*)d_in[2];
    const float* g_b0 = (const float*)d_in[3];
    const float* g_w1 = (const float*)d_in[4];
    const float* g_b1 = (const float*)d_in[5];
    const float* g_w2 = (const float*)d_in[6];
    const float* g_b2 = (const float*)d_in[7];
    const float* f_w0 = (const float*)d_in[8];
    const float* f_b0 = (const float*)d_in[9];
    const float* f_w1 = (const float*)d_in[10];
    const float* f_b1 = (const float*)d_in[11];
    float* out = (float*)d_out;

    setup_wfrag_kernel<<<256, 256>>>(g_w1, g_w2);
    precomp_kernel<<<dim3(8, BB), 256>>>(x, q, g_w0, g_b0);

    static int configured = 0;
    if (!configured) {
        cudaFuncSetAttribute(rn_mma_kernel, cudaFuncAttributeMaxDynamicSharedMemorySize,
                             SMEM_TOTAL);
        configured = 1;
    }
    rn_mma_kernel<<<dim3(NN, BB), 256, SMEM_TOTAL>>>(g_b1, g_b2);

    f_mlp_kernel<<<BB, 256>>>(f_w0, f_b0, f_w1, f_b1, out);
}

// round 15
// speedup vs baseline: 2.9343x; 2.0596x over previous
#include <cuda_runtime.h>
#include <cuda_fp16.h>
#include <cstdint>

#define BB 32
#define NN 64
#define DD 128
#define GH 256

// ---------------- smem byte offsets (main kernel) ----------------
#define A_OFF      0             // h0/h1 fp16 tile [64][256], swizzled (32KB)
#define B_OFF      32768         // two 64KB B-fragment buffers
#define ROWC_OFF   163840
#define B1S_OFF    164864
#define B2S_OFF    165888
#define RED_OFF    166912
#define SMEM_TOTAL 168960

// ---------------- helpers ----------------
__device__ __forceinline__ uint32_t pack_hf2(__half lo, __half hi) {
    return ((uint32_t)__half_as_ushort(hi) << 16) | __half_as_ushort(lo);
}
__device__ __forceinline__ float relu_f(float v) { return v > 0.f ? v : 0.f; }
// A tile byte offset: row-major [64][256] fp16, 512B rows, 16B-chunk XOR swizzle
__device__ __forceinline__ int a_off(int row, int k) {
    return row * 512 + ((((k >> 3) ^ (row & 7))) << 4) + ((k & 7) << 1);
}
__device__ __forceinline__ uint32_t smem_addr_u32(const void* p) {
    return (uint32_t)__cvta_generic_to_shared(p);
}
__device__ __forceinline__ void cp_async16(uint32_t saddr, const void* gptr) {
    asm volatile("cp.async.ca.shared.global [%0], [%1], 16;" :: "r"(saddr), "l"(gptr));
}
#define CP_COMMIT() asm volatile("cp.async.commit_group;" ::: "memory")
#define CP_WAIT(N)  asm volatile("cp.async.wait_group %0;" :: "n"(N) : "memory")

#define MMA_F16(D, A, B) \
    asm volatile("mma.sync.aligned.m16n8k16.row.col.f32.f16.f16.f32 " \
        "{%0,%1,%2,%3}, {%4,%5,%6,%7}, {%8,%9}, {%0,%1,%2,%3};" \
        : "+f"((D)[0]), "+f"((D)[1]), "+f"((D)[2]), "+f"((D)[3]) \
        : "r"((A)[0]), "r"((A)[1]), "r"((A)[2]), "r"((A)[3]), \
          "r"((B).x), "r"((B).y))

// ---------------- device scratch ----------------
__device__ float g_base[BB * NN * GH];
__device__ float g_rowc[BB * NN * GH];
__device__ float g_partial[BB * NN * GH];
__device__ float g_emb[BB * GH];
__device__ float g_h[BB * GH];
// B fragments (fp16), per-lane layout: uint2 [layer][part][kc][ks][ntg][lane]
__device__ __align__(16) uint2 g_wfrag[2 * 2 * 4 * 4 * 32 * 32];

// ---------------- kernel 0: build weight fragments (fp16 split) ----------------
__global__ void setup_wfrag_kernel(const float* __restrict__ w1, const float* __restrict__ w2) {
    int idx = blockIdx.x * 256 + threadIdx.x;        // 0..65535
    int lane = idx & 31;
    int ntg  = (idx >> 5) & 31;
    int ks   = (idx >> 10) & 3;
    int kc   = (idx >> 12) & 3;
    int p    = (idx >> 14) & 1;
    int l    = (idx >> 15) & 1;
    const float* W = l ? w2 : w1;
    int n  = ntg * 8 + (lane >> 2);
    int k0 = kc * 64 + ks * 16 + (lane & 3) * 2;

    __half v[4];
#pragma unroll
    for (int t = 0; t < 4; ++t) {
        int k = k0 + (t >> 1) * 8 + (t & 1);
        float wv = W[k * GH + n];
        __half hi = __float2half_rn(wv);
        v[t] = p ? __float2half_rn(wv - __half2float(hi)) : hi;
    }
    uint2 r;
    r.x = pack_hf2(v[0], v[1]);
    r.y = pack_hf2(v[2], v[3]);
    g_wfrag[idx] = r;
}

// ---------------- kernel 1: layer-0 factorization ----------------
__global__ void precomp_kernel(const float* __restrict__ x,
                               const float* __restrict__ q,
                               const float* __restrict__ w0,
                               const float* __restrict__ b0) {
    const int batch = blockIdx.y;
    const int i0 = blockIdx.x * 8;
    const int k = threadIdx.x;

    __shared__ float xs[8][DD];
    __shared__ float qs[DD];
    for (int idx = threadIdx.x; idx < 8 * DD; idx += 256) {
        int r = idx >> 7, d = idx & (DD - 1);
        xs[r][d] = x[(batch * NN + i0 + r) * DD + d];
    }
    if (threadIdx.x < DD) qs[threadIdx.x] = q[batch * DD + threadIdx.x];
    __syncthreads();

    float accA[8], accB[8];
#pragma unroll
    for (int r = 0; r < 8; ++r) { accA[r] = 0.f; accB[r] = 0.f; }
    float qacc = 0.f;

#pragma unroll 8
    for (int d = 0; d < DD; ++d) {
        float wa = w0[d * GH + k];
        float wb = w0[(DD + d) * GH + k];
        float wq = w0[(2 * DD + d) * GH + k];
        qacc += qs[d] * wq;
#pragma unroll
        for (int r = 0; r < 8; ++r) {
            accA[r] += xs[r][d] * wa;
            accB[r] += xs[r][d] * wb;
        }
    }
    qacc += b0[k];
#pragma unroll
    for (int r = 0; r < 8; ++r) {
        g_base[(batch * NN + i0 + r) * GH + k] = accA[r];
        g_rowc[(batch * NN + i0 + r) * GH + k] = accB[r] + qacc;
    }
}

// ---------------- kernel 2: fp16 tensor-core main (2-term split) ----------------
// grid (NN, BB). 8 warps: wm = w>>2 (rows 32), wn = w&3 (cols 64).
// Activations truncated to fp16 (A tile); weights split w_hi+w_lo (B fragments).
extern __shared__ char smem_raw[];

__global__ void __launch_bounds__(256, 1)
rn_mma_kernel(const float* __restrict__ b1, const float* __restrict__ b2) {
    const int batch = blockIdx.y;
    const int i = blockIdx.x;
    const int tid = threadIdx.x;
    const int w = tid >> 5;
    const int lane = tid & 31;
    const int wm = w >> 2;
    const int wn = w & 3;

    char* sm = smem_raw;
    float* rowcs = (float*)(sm + ROWC_OFF);
    float* b1s   = (float*)(sm + B1S_OFF);
    float* b2s   = (float*)(sm + B2S_OFF);
    float* red   = (float*)(sm + RED_OFF);

    rowcs[tid] = g_rowc[(batch * NN + i) * GH + tid];
    b1s[tid] = b1[tid];
    b2s[tid] = b2[tid];
    __syncthreads();

    // ---- build h0 (fp16, swizzled) ----
    const float* bp = g_base + (size_t)(batch * NN) * GH;
#pragma unroll 4
    for (int t = 0; t < 32; ++t) {
        int pi = t * 256 + tid;          // 0..8191 pairs
        int row = pi >> 7;
        int k = (pi & 127) * 2;
        float2 v = *(const float2*)&bp[row * GH + k];
        float a0 = relu_f(v.x + rowcs[k]);
        float a1 = relu_f(v.y + rowcs[k + 1]);
        *(uint32_t*)(sm + A_OFF + a_off(row, k)) =
            pack_hf2(__float2half_rn(a0), __float2half_rn(a1));
    }

    float acc[2][8][4];
#pragma unroll
    for (int mt = 0; mt < 2; ++mt)
#pragma unroll
        for (int nt = 0; nt < 8; ++nt)
#pragma unroll
            for (int e = 0; e < 4; ++e) acc[mt][nt][e] = 0.f;

    // prefetch chunk 0 (layer 0, kc 0)
    const uint4* wfrag4 = (const uint4*)g_wfrag;
    {
#pragma unroll
        for (int t = 0; t < 16; ++t) {
            int idx = t * 256 + tid;                 // 0..4095 uint4
            int part = idx >> 11, within = idx & 2047;
            cp_async16(smem_addr_u32(sm + B_OFF) + idx * 16,
                       wfrag4 + ((0 * 2 + part) * 4 + 0) * 2048 + within);
        }
        CP_COMMIT();
    }

#pragma unroll 1
    for (int c = 0; c < 8; ++c) {
        const int buf = c & 1;
        // prefetch chunk c+1 into other buffer
        if (c < 7) {
            int nl = (c + 1) >> 2, nkc = (c + 1) & 3, nbuf = (c + 1) & 1;
#pragma unroll
            for (int t = 0; t < 16; ++t) {
                int idx = t * 256 + tid;
                int part = idx >> 11, within = idx & 2047;
                cp_async16(smem_addr_u32(sm + B_OFF) + (size_t)nbuf * 65536 + idx * 16,
                           wfrag4 + ((nl * 2 + part) * 4 + nkc) * 2048 + within);
            }
            CP_COMMIT();
            CP_WAIT(1);
        } else {
            CP_WAIT(0);
        }
        __syncthreads();   // chunk c resident; all warps past previous iteration

        const uint2* Bs = (const uint2*)(sm + B_OFF + (size_t)buf * 65536);
        const int kc = c & 3;

#pragma unroll 1
        for (int ks = 0; ks < 4; ++ks) {
            const int kbase = kc * 64 + ks * 16;
            uint32_t ahi[2][4];
#pragma unroll
            for (int mt = 0; mt < 2; ++mt) {
                int r0 = wm * 32 + mt * 16 + (lane >> 2);
                int r1 = r0 + 8;
                int kA = kbase + (lane & 3) * 2;
                ahi[mt][0] = *(const uint32_t*)(sm + A_OFF + a_off(r0, kA));
                ahi[mt][1] = *(const uint32_t*)(sm + A_OFF + a_off(r1, kA));
                ahi[mt][2] = *(const uint32_t*)(sm + A_OFF + a_off(r0, kA + 8));
                ahi[mt][3] = *(const uint32_t*)(sm + A_OFF + a_off(r1, kA + 8));
            }
#pragma unroll
            for (int nt2 = 0; nt2 < 4; ++nt2) {
                int ntgA = wn * 8 + nt2 * 2;
                uint2 bh0 = Bs[(0 * 4 + ks) * 1024 + ntgA * 32 + lane];
                uint2 bh1 = Bs[(0 * 4 + ks) * 1024 + (ntgA + 1) * 32 + lane];
                uint2 bl0 = Bs[(1 * 4 + ks) * 1024 + ntgA * 32 + lane];
                uint2 bl1 = Bs[(1 * 4 + ks) * 1024 + (ntgA + 1) * 32 + lane];
                // a_hi * w_hi
                MMA_F16(acc[0][nt2 * 2], ahi[0], bh0);
                MMA_F16(acc[0][nt2 * 2 + 1], ahi[0], bh1);
                MMA_F16(acc[1][nt2 * 2], ahi[1], bh0);
                MMA_F16(acc[1][nt2 * 2 + 1], ahi[1], bh1);
                // a_hi * w_lo
                MMA_F16(acc[0][nt2 * 2], ahi[0], bl0);
                MMA_F16(acc[0][nt2 * 2 + 1], ahi[0], bl1);
                MMA_F16(acc[1][nt2 * 2], ahi[1], bl0);
                MMA_F16(acc[1][nt2 * 2 + 1], ahi[1], bl1);
            }
        }

        if (c == 3) {
            // ---- epilogue 1: h1 = relu(acc + b1) -> fp16 -> A ----
            __syncthreads();   // all h0 reads complete
#pragma unroll
            for (int mt = 0; mt < 2; ++mt)
#pragma unroll
                for (int nt = 0; nt < 8; ++nt) {
                    int r0 = wm * 32 + mt * 16 + (lane >> 2);
                    int r1 = r0 + 8;
                    int col = wn * 64 + nt * 8 + (lane & 3) * 2;
                    float b0v = b1s[col], b1v = b1s[col + 1];
                    float v00 = relu_f(acc[mt][nt][0] + b0v);
                    float v01 = relu_f(acc[mt][nt][1] + b1v);
                    float v10 = relu_f(acc[mt][nt][2] + b0v);
                    float v11 = relu_f(acc[mt][nt][3] + b1v);
                    *(uint32_t*)(sm + A_OFF + a_off(r0, col)) =
                        pack_hf2(__float2half_rn(v00), __float2half_rn(v01));
                    *(uint32_t*)(sm + A_OFF + a_off(r1, col)) =
                        pack_hf2(__float2half_rn(v10), __float2half_rn(v11));
                }
#pragma unroll
            for (int mt = 0; mt < 2; ++mt)
#pragma unroll
                for (int nt = 0; nt < 8; ++nt)
#pragma unroll
                    for (int e = 0; e < 4; ++e) acc[mt][nt][e] = 0.f;
        }
        __syncthreads();   // safe to overwrite buf[(c+2)&1] next iteration
    }

    // ---- epilogue 2: relu(acc + b2), reduce over rows (j) ----
#pragma unroll
    for (int nt = 0; nt < 8; ++nt) {
        int col = wn * 64 + nt * 8 + (lane & 3) * 2;
        float b0v = b2s[col], b1v = b2s[col + 1];
        float s0 = relu_f(acc[0][nt][0] + b0v) + relu_f(acc[0][nt][2] + b0v)
                 + relu_f(acc[1][nt][0] + b0v) + relu_f(acc[1][nt][2] + b0v);
        float s1 = relu_f(acc[0][nt][1] + b1v) + relu_f(acc[0][nt][3] + b1v)
                 + relu_f(acc[1][nt][1] + b1v) + relu_f(acc[1][nt][3] + b1v);
        s0 += __shfl_xor_sync(0xffffffffu, s0, 4);
        s0 += __shfl_xor_sync(0xffffffffu, s0, 8);
        s0 += __shfl_xor_sync(0xffffffffu, s0, 16);
        s1 += __shfl_xor_sync(0xffffffffu, s1, 4);
        s1 += __shfl_xor_sync(0xffffffffu, s1, 8);
        s1 += __shfl_xor_sync(0xffffffffu, s1, 16);
        if (lane < 4) {
            red[wm * GH + col] = s0;
            red[wm * GH + col + 1] = s1;
        }
    }
    __syncthreads();
    g_partial[(batch * NN + i) * GH + tid] = red[tid] + red[GH + tid];
}

// ---------------- kernel 3a: embedding reduce ----------------
__global__ void emb_kernel(int dummy) {
    const int batch = blockIdx.x;
    const int t = threadIdx.x;
    float s = 0.f;
    const float* gp = g_partial + (size_t)batch * NN * GH + t;
#pragma unroll 8
    for (int blk = 0; blk < NN; ++blk) s += gp[(size_t)blk * GH];
    g_emb[batch * GH + t] = s;
}

// ---------------- kernel 3b: f hidden layer (8-way k-split GEMV) ----------------
// grid (8, 32): block (g, batch) computes h[g*32 .. g*32+31].
__global__ void f_hidden_kernel(const float* __restrict__ fw0, const float* __restrict__ fb0) {
    const int batch = blockIdx.y;
    const int g = blockIdx.x;
    const int c = threadIdx.x & 31;     // col within group
    const int m8 = threadIdx.x >> 5;    // k-split 0..7
    const int col = g * 32 + c;

    __shared__ float embs[GH];
    __shared__ float part[8][33];
    embs[threadIdx.x] = g_emb[batch * GH + threadIdx.x];
    __syncthreads();

    float s = 0.f;
#pragma unroll 8
    for (int mm = 0; mm < 32; ++mm) {
        int m = m8 * 32 + mm;
        s += embs[m] * fw0[m * GH + col];
    }
    part[m8][c] = s;
    __syncthreads();

    if (threadIdx.x < 32) {
        float tot = 0.f;
#pragma unroll
        for (int p = 0; p < 8; ++p) tot += part[p][threadIdx.x];
        float v = tot + fb0[g * 32 + threadIdx.x];
        g_h[batch * GH + g * 32 + threadIdx.x] = v > 0.f ? v : 0.f;
    }
}

// ---------------- kernel 3c: f output layer ----------------
// grid (32): 8 threads per output col, 32 cols.
__global__ void f_out_kernel(const float* __restrict__ fw1, const float* __restrict__ fb1,
                             float* __restrict__ out) {
    const int batch = blockIdx.x;
    const int o = threadIdx.x & 31;
    const int p = threadIdx.x >> 5;

    __shared__ float part[8][33];
    float s = 0.f;
#pragma unroll 8
    for (int mm = 0; mm < 32; ++mm) {
        int n = p * 32 + mm;
        s += g_h[batch * GH + n] * fw1[n * 32 + o];
    }
    part[p][o] = s;
    __syncthreads();

    if (threadIdx.x < 32) {
        float tot = 0.f;
#pragma unroll
        for (int pp = 0; pp < 8; ++pp) tot += part[pp][threadIdx.x];
        out[batch * 32 + threadIdx.x] = tot + fb1[threadIdx.x];
    }
}

// ---------------- launch ----------------
extern "C" void kernel_launch(void* const* d_in, const int* in_sizes, int n_in,
                              void* d_out, int out_size) {
    const float* x    = (const float*)d_in[0];
    const float* q    = (const float*)d_in[1];
    const float* g_w0 = (const float*)d_in[2];
    const float* g_b0 = (const float*)d_in[3];
    const float* g_w1 = (const float*)d_in[4];
    const float* g_b1 = (const float*)d_in[5];
    const float* g_w2 = (const float*)d_in[6];
    const float* g_b2 = (const float*)d_in[7];
    const float* f_w0 = (const float*)d_in[8];
    const float* f_b0 = (const float*)d_in[9];
    const float* f_w1 = (const float*)d_in[10];
    const float* f_b1 = (const float*)d_in[11];
    float* out = (float*)d_out;

    setup_wfrag_kernel<<<256, 256>>>(g_w1, g_w2);
    precomp_kernel<<<dim3(8, BB), 256>>>(x, q, g_w0, g_b0);

    static int configured = 0;
    if (!configured) {
        cudaFuncSetAttribute(rn_mma_kernel, cudaFuncAttributeMaxDynamicSharedMemorySize,
                             SMEM_TOTAL);
        configured = 1;
    }
    rn_mma_kernel<<<dim3(NN, BB), 256, SMEM_TOTAL>>>(g_b1, g_b2);

    emb_kernel<<<BB, 256>>>(0);
    f_hidden_kernel<<<dim3(8, BB), 256>>>(f_w0, f_b0);
    f_out_kernel<<<BB, 256>>>(f_w1, f_b1, out);
}